// round 12
// baseline (speedup 1.0000x reference)
#include <cuda_runtime.h>
#include <cstdint>

#define TPB 128
#define NSTEP 7

typedef unsigned long long u64;

// ---------- f32x2 packed helpers ----------
__device__ __forceinline__ u64 pk(float lo, float hi) {
    u64 d; asm("mov.b64 %0, {%1, %2};" : "=l"(d) : "f"(lo), "f"(hi)); return d;
}
__device__ __forceinline__ void unpk(u64 d, float& lo, float& hi) {
    asm("mov.b64 {%0, %1}, %2;" : "=f"(lo), "=f"(hi) : "l"(d));
}
__device__ __forceinline__ u64 fma2_(u64 a, u64 b, u64 c) {
    u64 d; asm("fma.rn.f32x2 %0, %1, %2, %3;" : "=l"(d) : "l"(a), "l"(b), "l"(c)); return d;
}
__device__ __forceinline__ u64 add2_(u64 a, u64 b) {
    u64 d; asm("add.rn.f32x2 %0, %1, %2;" : "=l"(d) : "l"(a), "l"(b)); return d;
}
__device__ __forceinline__ float ftanh(float x) {
    float y; asm("tanh.approx.f32 %0, %1;" : "=f"(y) : "f"(x)); return y;
}
// Volatile LDS.128 of two u64 pairs — volatile so ptxas CANNOT hoist the
// weights into persistent registers (that's the whole point: regs stay ~40).
__device__ __forceinline__ void lds2(uint32_t addr, u64& lo, u64& hi) {
    asm volatile("ld.shared.v2.u64 {%0, %1}, [%2];"
                 : "=l"(lo), "=l"(hi) : "r"(addr));
}
__device__ __forceinline__ uint32_t s2u(const void* p) {
    uint32_t a;
    asm("{ .reg .u64 t; cvta.to.shared.u64 t, %1; cvt.u32.u64 %0, t; }"
        : "=r"(a) : "l"(p));
    return a;
}

// One GRU cell, hidden=2, weights streamed from smem just-in-time.
// smem weight layout per GRU (16 u64 pairs, lanes = hidden 0/1), slot order:
//  0:wr_x0 1:wr_x1 | 2:wr_b 3:wz_x0 | 4:wz_x1 5:wz_b | 6:wn_x0 7:wn_x1 |
//  8:wn_bi 9:wr_h0 | 10:wr_h1 11:wz_h0 | 12:wz_h1 13:wn_h0 | 14:wn_h1 15:wn_bh
// r/z weights+biases prescaled 0.5 (bih+bhh fused); n-gi unscaled; n-gh ×0.5.
// r = 0.5*(1+tanh(ur)); z likewise; arg = gi+gh + t_r*gh; n = tanh(arg).
__device__ __forceinline__ void gru_cell_s(u64 aa, u64 bb, float& h0, float& h1,
                                           uint32_t Wb) {
    u64 p0, p1, q0, q1;
    lds2(Wb +   0, p0, p1);            // wr_x0, wr_x1
    lds2(Wb +  16, q0, q1);            // wr_b,  wz_x0
    u64 xr = fma2_(p0, aa, fma2_(p1, bb, q0));
    lds2(Wb +  32, p0, p1);            // wz_x1, wz_b
    u64 xz = fma2_(q1, aa, fma2_(p0, bb, p1));
    lds2(Wb +  48, q0, q1);            // wn_x0, wn_x1
    lds2(Wb +  64, p0, p1);            // wn_bi, wr_h0
    u64 gi = fma2_(q0, aa, fma2_(q1, bb, p0));
    u64 hh0 = pk(h0, h0), hh1 = pk(h1, h1);
    lds2(Wb +  80, q0, q1);            // wr_h1, wz_h0
    u64 ur = fma2_(p1, hh0, fma2_(q0, hh1, xr));
    lds2(Wb +  96, p0, p1);            // wz_h1, wn_h0
    u64 uz = fma2_(q1, hh0, fma2_(p0, hh1, xz));
    lds2(Wb + 112, q0, q1);            // wn_h1, wn_bh
    u64 gh = fma2_(p1, hh0, fma2_(q0, hh1, q1));

    float ur0, ur1, uz0, uz1;
    unpk(ur, ur0, ur1); unpk(uz, uz0, uz1);
    float tr0 = ftanh(ur0), tr1 = ftanh(ur1);
    float tz0 = ftanh(uz0), tz1 = ftanh(uz1);

    u64 s   = add2_(gi, gh);
    u64 arg = fma2_(pk(tr0, tr1), gh, s);
    float a0, a1; unpk(arg, a0, a1);

    float n0 = ftanh(a0);
    float n1 = ftanh(a1);
    float z0 = fmaf(0.5f, tz0, 0.5f);
    float z1 = fmaf(0.5f, tz1, 0.5f);
    h0 = fmaf(z0, h0 - n0, n0);
    h1 = fmaf(z1, h1 - n1, n1);
}

// smem byte offsets of weight regions (within sw)
#define WB_UP   0
#define WB_DN   128
#define WB_OBS  256
#define WB_OUT  320
#define W_FLTS  84     // 336 bytes

__global__ void __launch_bounds__(TPB, 12)
rec_policy_kernel(const float* __restrict__ x,
                  const float* __restrict__ up_wih, const float* __restrict__ up_whh,
                  const float* __restrict__ up_bih, const float* __restrict__ up_bhh,
                  const float* __restrict__ dn_wih, const float* __restrict__ dn_whh,
                  const float* __restrict__ dn_bih, const float* __restrict__ dn_bhh,
                  const float* __restrict__ obs_w, const float* __restrict__ obs_b,
                  const float* __restrict__ out_w, const float* __restrict__ out_b,
                  float* __restrict__ out, int B) {
    __shared__ __align__(16) float sw[W_FLTS];
    __shared__ __align__(16) float s[TPB * 19];  // input + hu scratch + output (in-place)
    const int tid = threadIdx.x;
    const int b0  = blockIdx.x * TPB;
    const int nrows = min(TPB, B - b0);

    // ---- thread 0: compute packed+prescaled weights into smem (slot order) ----
    if (tid == 0) {
#pragma unroll
        for (int g = 0; g < 2; ++g) {
            const float* wih = g ? dn_wih : up_wih;
            const float* whh = g ? dn_whh : up_whh;
            const float* bih = g ? dn_bih : up_bih;
            const float* bhh = g ? dn_bhh : up_bhh;
            float* W = sw + g * 32;
            // slot k -> floats [2k, 2k+1] = (lane0, lane1)
            W[0]  = 0.5f * wih[0];  W[1]  = 0.5f * wih[2];   // wr_x0
            W[2]  = 0.5f * wih[1];  W[3]  = 0.5f * wih[3];   // wr_x1
            W[4]  = 0.5f * (bih[0] + bhh[0]);
            W[5]  = 0.5f * (bih[1] + bhh[1]);                // wr_b
            W[6]  = 0.5f * wih[4];  W[7]  = 0.5f * wih[6];   // wz_x0
            W[8]  = 0.5f * wih[5];  W[9]  = 0.5f * wih[7];   // wz_x1
            W[10] = 0.5f * (bih[2] + bhh[2]);
            W[11] = 0.5f * (bih[3] + bhh[3]);                // wz_b
            W[12] = wih[8];         W[13] = wih[10];         // wn_x0 (unscaled)
            W[14] = wih[9];         W[15] = wih[11];         // wn_x1
            W[16] = bih[4];         W[17] = bih[5];          // wn_bi
            W[18] = 0.5f * whh[0];  W[19] = 0.5f * whh[2];   // wr_h0
            W[20] = 0.5f * whh[1];  W[21] = 0.5f * whh[3];   // wr_h1
            W[22] = 0.5f * whh[4];  W[23] = 0.5f * whh[6];   // wz_h0
            W[24] = 0.5f * whh[5];  W[25] = 0.5f * whh[7];   // wz_h1
            W[26] = 0.5f * whh[8];  W[27] = 0.5f * whh[10];  // wn_h0
            W[28] = 0.5f * whh[9];  W[29] = 0.5f * whh[11];  // wn_h1
            W[30] = 0.5f * bhh[4];  W[31] = 0.5f * bhh[5];   // wn_bh
        }
#pragma unroll
        for (int j = 0; j < 7; ++j) {
            sw[64 + 2*j + 0] = obs_w[j];
            sw[64 + 2*j + 1] = obs_w[7 + j];
        }
        sw[64 + 14] = obs_b[0];
        sw[64 + 15] = obs_b[1];
        sw[80 + 0] = out_w[0];
        sw[80 + 1] = out_w[1];
        sw[80 + 2] = out_b[0];
        sw[80 + 3] = 0.0f;
    }

    // ---- stage input [nrows x 19] coalesced ----
    if (nrows == TPB) {
        const float4* src = (const float4*)(x + (size_t)b0 * 19);
        float4* dst = (float4*)s;
        constexpr int N4 = TPB * 19 / 4;    // 608
#pragma unroll
        for (int i = 0; i < (N4 + TPB - 1) / TPB; ++i) {
            int idx = tid + i * TPB;
            if (idx < N4) dst[idx] = src[idx];
        }
    } else {
        for (int idx = tid; idx < nrows * 19; idx += TPB)
            s[idx] = x[(size_t)b0 * 19 + idx];
    }
    __syncthreads();

    const uint32_t swb = s2u(sw);
    float* row = s + tid * 19;              // 19 odd -> conflict-free

    {
        // ---- up GRU; hu stored in-place over consumed inputs ----
        float h0 = 0.0f, h1 = 0.0f;
#pragma unroll
        for (int t = 0; t < NSTEP; ++t) {
            float a = row[5 + t], b = row[12 + t];
            gru_cell_s(pk(a, a), pk(b, b), h0, h1, swb + WB_UP);
            row[5 + t] = h0; row[12 + t] = h1;
        }

        // ---- obs linear (packed over output lanes), weights streamed ----
        float g0, g1;
        {
            u64 p0, p1, q0, q1;
            lds2(swb + WB_OBS +  0, p0, p1);   // ow0, ow1
            lds2(swb + WB_OBS + 16, q0, q1);   // ow2, ow3
            u64 c = fma2_(p0, pk(row[0], row[0]),
                    fma2_(p1, pk(row[1], row[1]),
                    fma2_(q0, pk(row[2], row[2]),
                    fma2_(q1, pk(row[3], row[3]), pk(0.0f, 0.0f)))));
            lds2(swb + WB_OBS + 32, p0, p1);   // ow4, ow5
            lds2(swb + WB_OBS + 48, q0, q1);   // ow6, obias
            c = fma2_(p0, pk(row[4], row[4]), add2_(c, q1));
            c = fma2_(p1, pk(h0, h0), c);
            c = fma2_(q0, pk(h1, h1), c);
            unpk(c, g0, g1);
        }

        // ---- down GRU; act[t] written in place into row[t] ----
        // Safe: row[0..4] dead after obs-linear; row[5],row[6] (hu t=0,1)
        // last read at down-steps 0,1, written only at t=5,6.
        float wox, woy, woz, wdum;
        {
            u64 p0, p1;
            lds2(swb + WB_OUT, p0, p1);
            unpk(p0, wox, woy);
            unpk(p1, woz, wdum);
        }
#pragma unroll
        for (int t = 0; t < NSTEP; ++t) {
            float hu0 = row[5 + t], hu1 = row[12 + t];
            gru_cell_s(pk(hu0, hu0), pk(hu1, hu1), g0, g1, swb + WB_DN);
            row[t] = fmaf(wox, g0, fmaf(woy, g1, woz));
        }
    }

    __syncthreads();

    // ---- stage output: out[r*7+c] = s[r*19+c], coalesced STG.32 ----
    {
        const int ntot = nrows * 7;
        for (int idx = tid; idx < ntot; idx += TPB) {
            int r = idx / 7;
            int c = idx - r * 7;
            out[(size_t)b0 * 7 + idx] = s[r * 19 + c];
        }
    }
}

extern "C" void kernel_launch(void* const* d_in, const int* in_sizes, int n_in,
                              void* d_out, int out_size) {
    const float* x      = (const float*)d_in[0];
    const float* up_wih = (const float*)d_in[1];
    const float* up_whh = (const float*)d_in[2];
    const float* up_bih = (const float*)d_in[3];
    const float* up_bhh = (const float*)d_in[4];
    const float* dn_wih = (const float*)d_in[5];
    const float* dn_whh = (const float*)d_in[6];
    const float* dn_bih = (const float*)d_in[7];
    const float* dn_bhh = (const float*)d_in[8];
    const float* obs_w  = (const float*)d_in[9];
    const float* obs_b  = (const float*)d_in[10];
    const float* out_w  = (const float*)d_in[11];
    const float* out_b  = (const float*)d_in[12];
    float* out = (float*)d_out;

    const int B = in_sizes[0] / 19;
    const int grid = (B + TPB - 1) / TPB;
    rec_policy_kernel<<<grid, TPB>>>(x,
                                     up_wih, up_whh, up_bih, up_bhh,
                                     dn_wih, dn_whh, dn_bih, dn_bhh,
                                     obs_w, obs_b, out_w, out_b,
                                     out, B);
}

// round 15
// speedup vs baseline: 1.0067x; 1.0067x over previous
#include <cuda_runtime.h>
#include <cstdint>

#define TPB 128
#define NSTEP 7

typedef unsigned long long u64;

// ---------- f32x2 packed helpers ----------
__device__ __forceinline__ u64 pk(float lo, float hi) {
    u64 d; asm("mov.b64 %0, {%1, %2};" : "=l"(d) : "f"(lo), "f"(hi)); return d;
}
__device__ __forceinline__ void unpk(u64 d, float& lo, float& hi) {
    asm("mov.b64 {%0, %1}, %2;" : "=f"(lo), "=f"(hi) : "l"(d));
}
__device__ __forceinline__ u64 fma2_(u64 a, u64 b, u64 c) {
    u64 d; asm("fma.rn.f32x2 %0, %1, %2, %3;" : "=l"(d) : "l"(a), "l"(b), "l"(c)); return d;
}
__device__ __forceinline__ u64 add2_(u64 a, u64 b) {
    u64 d; asm("add.rn.f32x2 %0, %1, %2;" : "=l"(d) : "l"(a), "l"(b)); return d;
}
__device__ __forceinline__ float ftanh(float x) {
    float y; asm("tanh.approx.f32 %0, %1;" : "=f"(y) : "f"(x)); return y;
}

// One GRU cell, hidden=2, weights register-resident.
// W layout (u64 pairs, lanes = hidden index 0/1):
//  [0..4]   r: wx0, wx1, wh0, wh1, bias (prescaled 0.5; bih+bhh fused)
//  [5..9]   z: same
//  [10..12] n gi: nx0, nx1, nbi  (UNscaled)
//  [13..15] n gh: nh0, nh1, nbh  (prescaled 0.5)
// r = 0.5*(1+tanh(u_r)); z = 0.5*(1+tanh(u_z))
// arg = gi + gh + t_r*gh (== i_n + r*h_n);  n = tanh(arg)
__device__ __forceinline__ void gru_cell(u64 aa, u64 bb, float& h0, float& h1,
                                         const u64* __restrict__ W) {
    u64 xr = fma2_(W[0],  aa, fma2_(W[1],  bb, W[4]));
    u64 xz = fma2_(W[5],  aa, fma2_(W[6],  bb, W[9]));
    u64 gi = fma2_(W[10], aa, fma2_(W[11], bb, W[12]));
    u64 hh0 = pk(h0, h0), hh1 = pk(h1, h1);
    u64 ur = fma2_(W[2],  hh0, fma2_(W[3],  hh1, xr));
    u64 uz = fma2_(W[7],  hh0, fma2_(W[8],  hh1, xz));
    u64 gh = fma2_(W[13], hh0, fma2_(W[14], hh1, W[15]));

    float ur0, ur1, uz0, uz1;
    unpk(ur, ur0, ur1); unpk(uz, uz0, uz1);
    float tr0 = ftanh(ur0), tr1 = ftanh(ur1);
    float tz0 = ftanh(uz0), tz1 = ftanh(uz1);

    u64 s   = add2_(gi, gh);
    u64 arg = fma2_(pk(tr0, tr1), gh, s);
    float a0, a1; unpk(arg, a0, a1);

    float n0 = ftanh(a0);
    float n1 = ftanh(a1);
    float z0 = fmaf(0.5f, tz0, 0.5f);
    float z1 = fmaf(0.5f, tz1, 0.5f);
    h0 = fmaf(z0, h0 - n0, n0);
    h1 = fmaf(z1, h1 - n1, n1);
}

// smem float offsets for prepped weights
#define W_UP   0
#define W_DN   32
#define W_OBS  64
#define W_OUT  80
#define W_FLTS 84

__global__ void __launch_bounds__(TPB, 10)
rec_policy_kernel(const float* __restrict__ x,
                  const float* __restrict__ up_wih, const float* __restrict__ up_whh,
                  const float* __restrict__ up_bih, const float* __restrict__ up_bhh,
                  const float* __restrict__ dn_wih, const float* __restrict__ dn_whh,
                  const float* __restrict__ dn_bih, const float* __restrict__ dn_bhh,
                  const float* __restrict__ obs_w, const float* __restrict__ obs_b,
                  const float* __restrict__ out_w, const float* __restrict__ out_b,
                  float* __restrict__ out, int B) {
    __shared__ __align__(16) float sw[W_FLTS];
    __shared__ __align__(16) float s[TPB * 19];  // input + hu scratch + output (in-place)
    const int tid = threadIdx.x;
    const int b0  = blockIdx.x * TPB;
    const int nrows = min(TPB, B - b0);

    // ---- thread 0: compute packed+prescaled weights into smem ----
    if (tid == 0) {
#pragma unroll
        for (int g = 0; g < 2; ++g) {
            const float* wih = g ? dn_wih : up_wih;
            const float* whh = g ? dn_whh : up_whh;
            const float* bih = g ? dn_bih : up_bih;
            const float* bhh = g ? dn_bhh : up_bhh;
            float* W = sw + (g ? W_DN : W_UP);
#pragma unroll
            for (int G = 0; G < 2; ++G) {    // r (rows 0,1), z (rows 2,3)
                float* p = W + G * 10;
                p[0] = 0.5f * wih[4*G + 0]; p[1] = 0.5f * wih[4*G + 2];
                p[2] = 0.5f * wih[4*G + 1]; p[3] = 0.5f * wih[4*G + 3];
                p[4] = 0.5f * whh[4*G + 0]; p[5] = 0.5f * whh[4*G + 2];
                p[6] = 0.5f * whh[4*G + 1]; p[7] = 0.5f * whh[4*G + 3];
                p[8] = 0.5f * (bih[2*G + 0] + bhh[2*G + 0]);
                p[9] = 0.5f * (bih[2*G + 1] + bhh[2*G + 1]);
            }
            // n gate (rows 4,5): gi unscaled, gh scaled by 0.5
            W[20] = wih[8];  W[21] = wih[10];
            W[22] = wih[9];  W[23] = wih[11];
            W[24] = bih[4];  W[25] = bih[5];
            W[26] = 0.5f * whh[8]; W[27] = 0.5f * whh[10];
            W[28] = 0.5f * whh[9]; W[29] = 0.5f * whh[11];
            W[30] = 0.5f * bhh[4]; W[31] = 0.5f * bhh[5];
        }
#pragma unroll
        for (int j = 0; j < 7; ++j) {
            sw[W_OBS + 2*j + 0] = obs_w[j];
            sw[W_OBS + 2*j + 1] = obs_w[7 + j];
        }
        sw[W_OBS + 14] = obs_b[0];
        sw[W_OBS + 15] = obs_b[1];
        sw[W_OUT + 0] = out_w[0];
        sw[W_OUT + 1] = out_w[1];
        sw[W_OUT + 2] = out_b[0];
        sw[W_OUT + 3] = 0.0f;
    }

    // ---- stage input [nrows x 19] coalesced ----
    if (nrows == TPB) {
        const float4* src = (const float4*)(x + (size_t)b0 * 19);
        float4* dst = (float4*)s;
        constexpr int N4 = TPB * 19 / 4;    // 608
#pragma unroll
        for (int i = 0; i < (N4 + TPB - 1) / TPB; ++i) {
            int idx = tid + i * TPB;
            if (idx < N4) dst[idx] = src[idx];
        }
    } else {
        for (int idx = tid; idx < nrows * 19; idx += TPB)
            s[idx] = x[(size_t)b0 * 19 + idx];
    }
    __syncthreads();

    float* row = s + tid * 19;              // 19 odd -> conflict-free

    {
        // ---- up GRU; weights in regs (4x LDS.128), hu stored in-place ----
        u64 UW[16];
        {
            const ulonglong2* p = (const ulonglong2*)(sw + W_UP);
#pragma unroll
            for (int i = 0; i < 8; ++i) { ulonglong2 v = p[i]; UW[2*i] = v.x; UW[2*i+1] = v.y; }
        }
        float h0 = 0.0f, h1 = 0.0f;
#pragma unroll
        for (int t = 0; t < NSTEP; ++t) {
            float a = row[5 + t], b = row[12 + t];
            gru_cell(pk(a, a), pk(b, b), h0, h1, UW);
            row[5 + t] = h0; row[12 + t] = h1;   // hu in-place over consumed inputs
        }

        // ---- obs linear (packed over output lanes) ----
        float g0, g1;
        {
            u64 OW[8];
            const ulonglong2* p = (const ulonglong2*)(sw + W_OBS);
#pragma unroll
            for (int i = 0; i < 4; ++i) { ulonglong2 v = p[i]; OW[2*i] = v.x; OW[2*i+1] = v.y; }
            u64 c = OW[7];
#pragma unroll
            for (int j = 0; j < 5; ++j) {
                float o = row[j];
                c = fma2_(OW[j], pk(o, o), c);
            }
            c = fma2_(OW[5], pk(h0, h0), c);
            c = fma2_(OW[6], pk(h1, h1), c);
            unpk(c, g0, g1);
        }

        // ---- down GRU; act[t] written in place into row[t] ----
        // Safe: row[0..4] (obs) dead after obs-linear; row[5],row[6] (hu t=0,1)
        // last read at down-steps 0,1, written only at t=5,6.
        u64 DW[16];
        {
            const ulonglong2* p = (const ulonglong2*)(sw + W_DN);
#pragma unroll
            for (int i = 0; i < 8; ++i) { ulonglong2 v = p[i]; DW[2*i] = v.x; DW[2*i+1] = v.y; }
        }
        const float4 wo = *(const float4*)(sw + W_OUT);
#pragma unroll
        for (int t = 0; t < NSTEP; ++t) {
            float hu0 = row[5 + t], hu1 = row[12 + t];
            gru_cell(pk(hu0, hu0), pk(hu1, hu1), g0, g1, DW);
            row[t] = fmaf(wo.x, g0, fmaf(wo.y, g1, wo.z));
        }
    }

    __syncthreads();

    // ---- stage output: out[r*7+c] = s[r*19+c], coalesced STG.32 ----
    {
        const int ntot = nrows * 7;
        for (int idx = tid; idx < ntot; idx += TPB) {
            int r = idx / 7;
            int c = idx - r * 7;
            out[(size_t)b0 * 7 + idx] = s[r * 19 + c];
        }
    }
}

extern "C" void kernel_launch(void* const* d_in, const int* in_sizes, int n_in,
                              void* d_out, int out_size) {
    const float* x      = (const float*)d_in[0];
    const float* up_wih = (const float*)d_in[1];
    const float* up_whh = (const float*)d_in[2];
    const float* up_bih = (const float*)d_in[3];
    const float* up_bhh = (const float*)d_in[4];
    const float* dn_wih = (const float*)d_in[5];
    const float* dn_whh = (const float*)d_in[6];
    const float* dn_bih = (const float*)d_in[7];
    const float* dn_bhh = (const float*)d_in[8];
    const float* obs_w  = (const float*)d_in[9];
    const float* obs_b  = (const float*)d_in[10];
    const float* out_w  = (const float*)d_in[11];
    const float* out_b  = (const float*)d_in[12];
    float* out = (float*)d_out;

    const int B = in_sizes[0] / 19;
    const int grid = (B + TPB - 1) / TPB;
    rec_policy_kernel<<<grid, TPB>>>(x,
                                     up_wih, up_whh, up_bih, up_bhh,
                                     dn_wih, dn_whh, dn_bih, dn_bhh,
                                     obs_w, obs_b, out_w, out_b,
                                     out, B);
}